// round 1
// baseline (speedup 1.0000x reference)
#include <cuda_runtime.h>
#include <math.h>

#define N_TOK 1024
#define HDIM  1024
#define IDIM  1024
#define NEXP  32
#define TOPK  4
#define NSLOT (N_TOK*TOPK)

#define BM 64
#define BN 64
#define BK 32

// ---------------- device scratch (no allocations allowed) ----------------
__device__ float g_t[N_TOK*HDIM];          // rmsnormed activations, 4MB
__device__ float g_a[NSLOT*IDIM];          // swiglu outputs per slot, 16MB
__device__ int   g_counts[NEXP];
__device__ int   g_offsets[NEXP+1];
__device__ int   g_cursor[NEXP];
__device__ int   g_topidx[NSLOT];
__device__ float g_topw[NSLOT];
__device__ int   g_slot_tok[NSLOT];
__device__ float g_slot_w[NSLOT];

__constant__ float c_fp4[16] = {0.f, .5f, 1.f, 1.5f, 2.f, 3.f, 4.f, 6.f,
                                -0.f,-.5f,-1.f,-1.5f,-2.f,-3.f,-4.f,-6.f};

// ---------------- k0: zero counters ----------------
__global__ void k0_zero() {
    int i = threadIdx.x;
    if (i < NEXP) { g_counts[i] = 0; g_cursor[i] = 0; }
}

// ---------------- k1: rmsnorm + residual init + gate + top4 ----------------
__global__ __launch_bounds__(256) void k1_norm_gate(
    const float* __restrict__ x, const float* __restrict__ norm_w,
    const float* __restrict__ gate_w, const float* __restrict__ gate_b,
    float* __restrict__ out)
{
    int tok = blockIdx.x;
    int tid = threadIdx.x;
    __shared__ float s_t[HDIM];
    __shared__ float s_red[8];
    __shared__ float s_log[NEXP];

    const float* xr = x + (size_t)tok * HDIM;
    float ss = 0.f;
    for (int i = tid; i < HDIM; i += 256) { float v = xr[i]; ss += v*v; s_t[i] = v; }
    #pragma unroll
    for (int o = 16; o; o >>= 1) ss += __shfl_down_sync(0xffffffffu, ss, o);
    if ((tid & 31) == 0) s_red[tid >> 5] = ss;
    __syncthreads();
    if (tid < 8) {
        float v = s_red[tid];
        #pragma unroll
        for (int o = 4; o; o >>= 1) v += __shfl_down_sync(0xffu, v, o);
        if (tid == 0) s_red[0] = v;
    }
    __syncthreads();
    float scale = rsqrtf(s_red[0] * (1.f / HDIM) + 1e-5f);
    for (int i = tid; i < HDIM; i += 256) {
        float t = s_t[i] * scale * norm_w[i];
        s_t[i] = t;
        g_t[(size_t)tok * HDIM + i] = t;
        out[(size_t)tok * HDIM + i] = xr[i];   // residual init
    }
    __syncthreads();

    // logits: 8 warps, 4 experts each
    int warp = tid >> 5, lane = tid & 31;
    for (int e = warp; e < NEXP; e += 8) {
        const float* gw = gate_w + (size_t)e * HDIM;
        float acc = 0.f;
        for (int i = lane; i < HDIM; i += 32) acc += s_t[i] * gw[i];
        #pragma unroll
        for (int o = 16; o; o >>= 1) acc += __shfl_down_sync(0xffffffffu, acc, o);
        if (lane == 0) s_log[e] = acc + gate_b[e];
    }
    __syncthreads();

    if (tid == 0) {
        int idx[TOPK]; float val[TOPK];
        unsigned mask = 0;
        #pragma unroll
        for (int k = 0; k < TOPK; k++) {
            float best = -1e30f; int bi = 0;
            for (int e = 0; e < NEXP; e++)
                if (!((mask >> e) & 1u) && s_log[e] > best) { best = s_log[e]; bi = e; }
            mask |= 1u << bi; idx[k] = bi; val[k] = best;
        }
        float mx = val[0];
        float se = 0.f;
        #pragma unroll
        for (int k = 0; k < TOPK; k++) { val[k] = expf(val[k] - mx); se += val[k]; }
        float inv = 1.f / se;
        #pragma unroll
        for (int k = 0; k < TOPK; k++) {
            g_topidx[tok*TOPK + k] = idx[k];
            g_topw[tok*TOPK + k]  = val[k] * inv;
            atomicAdd(&g_counts[idx[k]], 1);
        }
    }
}

// ---------------- k2: exclusive scan ----------------
__global__ void k2_scan() {
    if (threadIdx.x == 0) {
        int s = 0;
        for (int e = 0; e < NEXP; e++) { g_offsets[e] = s; s += g_counts[e]; }
        g_offsets[NEXP] = s;
    }
}

// ---------------- k3: scatter into expert-sorted slots ----------------
__global__ void k3_scatter() {
    int i = blockIdx.x * blockDim.x + threadIdx.x;
    if (i < NSLOT) {
        int e = g_topidx[i];
        int pos = g_offsets[e] + atomicAdd(&g_cursor[e], 1);
        g_slot_tok[pos] = i >> 2;
        g_slot_w[pos]   = g_topw[i];
    }
}

// ---------------- k4: grouped GEMM mlp1 + swiglu ----------------
// C[m][n] = sum_k t[tok_m][k] * w1[e][row_n][k];  rows: even=gate, odd=lin
__global__ __launch_bounds__(256) void k4_mlp1(
    const int* __restrict__ blocks, const int* __restrict__ scales,
    const float* __restrict__ bias)
{
    int e  = blockIdx.x;
    int nt = blockIdx.y;                 // 2I/BN = 32 tiles
    int cnt = g_counts[e];
    int m0 = blockIdx.z * BM;
    if (m0 >= cnt) return;
    int off = g_offsets[e];

    __shared__ float As[BK][BM+1];
    __shared__ float Bs[BK][BN+1];
    __shared__ int   s_tok[BM];

    int tid = threadIdx.x;
    if (tid < BM) {
        int m = m0 + tid;
        s_tok[tid] = (m < cnt) ? g_slot_tok[off + m] : -1;
    }
    __syncthreads();

    int tx = tid & 15, ty = tid >> 4;
    float acc[4][4] = {};

    const int ROWS = 2*IDIM, GRPS = HDIM/32;
    for (int k0 = 0; k0 < HDIM; k0 += BK) {
        // load A tile (tokens x 32)
        #pragma unroll
        for (int it = 0; it < (BM*BK)/256; it++) {
            int i = tid + it*256;
            int m = i >> 5, k = i & 31;
            int tok = s_tok[m];
            As[k][m] = (tok >= 0) ? g_t[(size_t)tok*HDIM + k0 + k] : 0.f;
        }
        // load + dequant B tile (64 rows x one 32-wide group)
        int g = k0 >> 5;
        #pragma unroll
        for (int it = 0; it < (BN*16)/256; it++) {
            int i = tid + it*256;
            int r = i >> 4, b = i & 15;
            size_t gi = ((size_t)e*ROWS + (nt*BN + r)) * GRPS + g;
            int word = blocks[gi*16 + b];
            float f = __int_as_float(scales[gi] << 23);  // 2^(scale-127)
            Bs[2*b  ][r] = c_fp4[word & 15]        * f;
            Bs[2*b+1][r] = c_fp4[(word >> 4) & 15] * f;
        }
        __syncthreads();
        #pragma unroll
        for (int k = 0; k < BK; k++) {
            float a[4], b[4];
            #pragma unroll
            for (int r = 0; r < 4; r++) a[r] = As[k][ty*4 + r];
            #pragma unroll
            for (int c = 0; c < 4; c++) b[c] = Bs[k][tx*4 + c];
            #pragma unroll
            for (int r = 0; r < 4; r++)
                #pragma unroll
                for (int c = 0; c < 4; c++) acc[r][c] += a[r] * b[c];
        }
        __syncthreads();
    }

    // epilogue: bias + swiglu, write g_a
    #pragma unroll
    for (int r = 0; r < 4; r++) {
        int m = m0 + ty*4 + r;
        if (m >= cnt) continue;
        int slot = off + m;
        #pragma unroll
        for (int p = 0; p < 2; p++) {
            int rowg = nt*BN + tx*4 + 2*p;          // gate row (even)
            float hg = acc[r][2*p]   + bias[(size_t)e*ROWS + rowg];
            float hl = acc[r][2*p+1] + bias[(size_t)e*ROWS + rowg + 1];
            hg = fminf(hg, 7.f);
            hl = fminf(fmaxf(hl, -7.f), 7.f);
            float aa = hg * (1.f / (1.f + expf(-1.702f * hg))) * (hl + 1.f);
            g_a[(size_t)slot*IDIM + (rowg >> 1)] = aa;
        }
    }
}

// ---------------- k5: grouped GEMM mlp2 + weighted scatter-add ----------------
__global__ __launch_bounds__(256) void k5_mlp2(
    const int* __restrict__ blocks, const int* __restrict__ scales,
    const float* __restrict__ bias, float* __restrict__ out)
{
    int e  = blockIdx.x;
    int nt = blockIdx.y;                 // H/BN = 16 tiles
    int cnt = g_counts[e];
    int m0 = blockIdx.z * BM;
    if (m0 >= cnt) return;
    int off = g_offsets[e];

    __shared__ float As[BK][BM+1];
    __shared__ float Bs[BK][BN+1];
    __shared__ int   s_tok[BM];
    __shared__ float s_w[BM];

    int tid = threadIdx.x;
    if (tid < BM) {
        int m = m0 + tid;
        s_tok[tid] = (m < cnt) ? g_slot_tok[off + m] : -1;
        s_w[tid]   = (m < cnt) ? g_slot_w[off + m] : 0.f;
    }
    __syncthreads();

    int tx = tid & 15, ty = tid >> 4;
    float acc[4][4] = {};

    const int ROWS = HDIM, GRPS = IDIM/32;
    for (int k0 = 0; k0 < IDIM; k0 += BK) {
        #pragma unroll
        for (int it = 0; it < (BM*BK)/256; it++) {
            int i = tid + it*256;
            int m = i >> 5, k = i & 31;
            int slot = off + m0 + m;
            As[k][m] = (m0 + m < cnt) ? g_a[(size_t)slot*IDIM + k0 + k] : 0.f;
        }
        int g = k0 >> 5;
        #pragma unroll
        for (int it = 0; it < (BN*16)/256; it++) {
            int i = tid + it*256;
            int r = i >> 4, b = i & 15;
            size_t gi = ((size_t)e*ROWS + (nt*BN + r)) * GRPS + g;
            int word = blocks[gi*16 + b];
            float f = __int_as_float(scales[gi] << 23);
            Bs[2*b  ][r] = c_fp4[word & 15]        * f;
            Bs[2*b+1][r] = c_fp4[(word >> 4) & 15] * f;
        }
        __syncthreads();
        #pragma unroll
        for (int k = 0; k < BK; k++) {
            float a[4], b[4];
            #pragma unroll
            for (int r = 0; r < 4; r++) a[r] = As[k][ty*4 + r];
            #pragma unroll
            for (int c = 0; c < 4; c++) b[c] = Bs[k][tx*4 + c];
            #pragma unroll
            for (int r = 0; r < 4; r++)
                #pragma unroll
                for (int c = 0; c < 4; c++) acc[r][c] += a[r] * b[c];
        }
        __syncthreads();
    }

    #pragma unroll
    for (int r = 0; r < 4; r++) {
        int mi = ty*4 + r;
        if (m0 + mi >= cnt) continue;
        int tok = s_tok[mi];
        float rw = s_w[mi];
        #pragma unroll
        for (int c = 0; c < 4; c++) {
            int col = nt*BN + tx*4 + c;
            float y = acc[r][c] + bias[(size_t)e*HDIM + col];
            atomicAdd(&out[(size_t)tok*HDIM + col], rw * y);
        }
    }
}

// ---------------- launch ----------------
extern "C" void kernel_launch(void* const* d_in, const int* in_sizes, int n_in,
                              void* d_out, int out_size)
{
    const float* x          = (const float*)d_in[0];
    const float* norm_w     = (const float*)d_in[1];
    const float* gate_w     = (const float*)d_in[2];
    const float* gate_b     = (const float*)d_in[3];
    const float* mlp1_bias  = (const float*)d_in[4];
    const float* mlp2_bias  = (const float*)d_in[5];
    const int*   mlp1_blocks= (const int*)d_in[6];
    const int*   mlp1_scales= (const int*)d_in[7];
    const int*   mlp2_blocks= (const int*)d_in[8];
    const int*   mlp2_scales= (const int*)d_in[9];
    float* out = (float*)d_out;

    k0_zero<<<1, 32>>>();
    k1_norm_gate<<<N_TOK, 256>>>(x, norm_w, gate_w, gate_b, out);
    k2_scan<<<1, 1>>>();
    k3_scatter<<<NSLOT/256, 256>>>();
    dim3 g4(NEXP, (2*IDIM)/BN, N_TOK/BM);   // (32, 32, 16), early-exit on m-tiles
    k4_mlp1<<<g4, 256>>>(mlp1_blocks, mlp1_scales, mlp1_bias);
    dim3 g5(NEXP, HDIM/BN, N_TOK/BM);       // (32, 16, 16)
    k5_mlp2<<<g5, 256>>>(mlp2_blocks, mlp2_scales, mlp2_bias, out);
}

// round 2
// speedup vs baseline: 1.5343x; 1.5343x over previous
#include <cuda_runtime.h>
#include <math.h>

#define N_TOK 1024
#define HDIM  1024
#define IDIM  1024
#define NEXP  32
#define TOPK  4
#define NSLOT (N_TOK*TOPK)

#define BM 128
#define BN 128
#define BK 32

// ---------------- device scratch ----------------
__device__ float g_t[N_TOK*HDIM];          // rmsnormed activations (fp32)
__device__ float g_a[NSLOT*IDIM];          // swiglu outputs per slot (fp32)
__device__ int   g_counts[NEXP];
__device__ int   g_offsets[NEXP+1];
__device__ int   g_cursor[NEXP];
__device__ int   g_topidx[NSLOT];
__device__ float g_topw[NSLOT];
__device__ int   g_slot_tok[NSLOT];
__device__ float g_slot_w[NSLOT];

__constant__ float c_fp4[16] = {0.f, .5f, 1.f, 1.5f, 2.f, 3.f, 4.f, 6.f,
                                -0.f,-.5f,-1.f,-1.5f,-2.f,-3.f,-4.f,-6.f};

// swizzled smem index: 32 cols per row, xor low k-bits with row low bits
#define SWZ(row,k) (((row)<<5) + ((k) ^ (((row)&3)<<3)))

__device__ __forceinline__ unsigned f2tf(float f) {
    unsigned r; asm("cvt.rna.tf32.f32 %0, %1;" : "=r"(r) : "f"(f)); return r;
}

__device__ __forceinline__ void mma_tf32(float c[4], const unsigned a[4], const unsigned b[2]) {
    asm volatile("mma.sync.aligned.m16n8k8.row.col.f32.tf32.tf32.f32 "
        "{%0,%1,%2,%3}, {%4,%5,%6,%7}, {%8,%9}, {%0,%1,%2,%3};"
        : "+f"(c[0]), "+f"(c[1]), "+f"(c[2]), "+f"(c[3])
        : "r"(a[0]), "r"(a[1]), "r"(a[2]), "r"(a[3]), "r"(b[0]), "r"(b[1]));
}

// ---------------- k0: zero counters ----------------
__global__ void k0_zero() {
    int i = threadIdx.x;
    if (i < NEXP) { g_counts[i] = 0; g_cursor[i] = 0; }
}

// ---------------- k1: rmsnorm + residual init + gate + top4 ----------------
__global__ __launch_bounds__(256) void k1_norm_gate(
    const float* __restrict__ x, const float* __restrict__ norm_w,
    const float* __restrict__ gate_w, const float* __restrict__ gate_b,
    float* __restrict__ out)
{
    int tok = blockIdx.x;
    int tid = threadIdx.x;
    __shared__ float s_t[HDIM];
    __shared__ float s_red[8];
    __shared__ float s_log[NEXP];

    const float* xr = x + (size_t)tok * HDIM;
    float ss = 0.f;
    for (int i = tid; i < HDIM; i += 256) { float v = xr[i]; ss += v*v; s_t[i] = v; }
    #pragma unroll
    for (int o = 16; o; o >>= 1) ss += __shfl_down_sync(0xffffffffu, ss, o);
    if ((tid & 31) == 0) s_red[tid >> 5] = ss;
    __syncthreads();
    if (tid < 8) {
        float v = s_red[tid];
        #pragma unroll
        for (int o = 4; o; o >>= 1) v += __shfl_down_sync(0xffu, v, o);
        if (tid == 0) s_red[0] = v;
    }
    __syncthreads();
    float scale = rsqrtf(s_red[0] * (1.f / HDIM) + 1e-5f);
    for (int i = tid; i < HDIM; i += 256) {
        float t = s_t[i] * scale * norm_w[i];
        s_t[i] = t;
        g_t[(size_t)tok * HDIM + i] = t;
        out[(size_t)tok * HDIM + i] = xr[i];   // residual init
    }
    __syncthreads();

    int warp = tid >> 5, lane = tid & 31;
    for (int e = warp; e < NEXP; e += 8) {
        const float* gw = gate_w + (size_t)e * HDIM;
        float acc = 0.f;
        for (int i = lane; i < HDIM; i += 32) acc += s_t[i] * gw[i];
        #pragma unroll
        for (int o = 16; o; o >>= 1) acc += __shfl_down_sync(0xffffffffu, acc, o);
        if (lane == 0) s_log[e] = acc + gate_b[e];
    }
    __syncthreads();

    if (tid == 0) {
        int idx[TOPK]; float val[TOPK];
        unsigned mask = 0;
        #pragma unroll
        for (int k = 0; k < TOPK; k++) {
            float best = -1e30f; int bi = 0;
            for (int e = 0; e < NEXP; e++)
                if (!((mask >> e) & 1u) && s_log[e] > best) { best = s_log[e]; bi = e; }
            mask |= 1u << bi; idx[k] = bi; val[k] = best;
        }
        float mx = val[0];
        float se = 0.f;
        #pragma unroll
        for (int k = 0; k < TOPK; k++) { val[k] = expf(val[k] - mx); se += val[k]; }
        float inv = 1.f / se;
        #pragma unroll
        for (int k = 0; k < TOPK; k++) {
            g_topidx[tok*TOPK + k] = idx[k];
            g_topw[tok*TOPK + k]  = val[k] * inv;
            atomicAdd(&g_counts[idx[k]], 1);
        }
    }
}

// ---------------- k2: exclusive scan ----------------
__global__ void k2_scan() {
    if (threadIdx.x == 0) {
        int s = 0;
        for (int e = 0; e < NEXP; e++) { g_offsets[e] = s; s += g_counts[e]; }
        g_offsets[NEXP] = s;
    }
}

// ---------------- k3: scatter ----------------
__global__ void k3_scatter() {
    int i = blockIdx.x * blockDim.x + threadIdx.x;
    if (i < NSLOT) {
        int e = g_topidx[i];
        int pos = g_offsets[e] + atomicAdd(&g_cursor[e], 1);
        g_slot_tok[pos] = i >> 2;
        g_slot_w[pos]   = g_topw[i];
    }
}

// ---------------- k4: tensor-core grouped GEMM mlp1 + swiglu ----------------
__global__ __launch_bounds__(256, 2) void k4_mlp1(
    const int* __restrict__ blocks, const int* __restrict__ scales,
    const float* __restrict__ bias)
{
    int e  = blockIdx.x;
    int nt = blockIdx.y;                 // 2I/BN = 16 tiles
    int cnt = g_counts[e];
    int m0 = blockIdx.z * BM;
    if (m0 >= cnt) return;
    int off = g_offsets[e];

    __shared__ unsigned As[BM*32];
    __shared__ unsigned Bs[BN*32];
    __shared__ int s_tok[BM];

    int tid = threadIdx.x;
    for (int i = tid; i < BM; i += 256) {
        int m = m0 + i;
        s_tok[i] = (m < cnt) ? g_slot_tok[off + m] : -1;
    }
    __syncthreads();

    int lane = tid & 31, wid = tid >> 5;
    int wm = wid >> 1, wn = wid & 1;     // 4m x 2n warps, warp tile 32x64
    float acc[2][8][4] = {};

    const int ROWS = 2*IDIM, GRPS = HDIM/32;
    for (int k0 = 0; k0 < HDIM; k0 += BK) {
        // A tile: 128 x 32, tf32 in smem
        #pragma unroll
        for (int it = 0; it < (BM*32)/256; it++) {
            int i = tid + it*256;
            int m = i >> 5, k = i & 31;
            int tok = s_tok[m];
            float v = (tok >= 0) ? g_t[(size_t)tok*HDIM + k0 + k] : 0.f;
            As[SWZ(m, k)] = f2tf(v);
        }
        // B tile: 128 rows x one 32-wide mxfp4 group (exact in tf32)
        int g = k0 >> 5;
        #pragma unroll
        for (int it = 0; it < (BN*16)/256; it++) {
            int i = tid + it*256;
            int r = i >> 4, b = i & 15;
            size_t gi = ((size_t)e*ROWS + (nt*BN + r)) * GRPS + g;
            int word = blocks[gi*16 + b];
            float f = __int_as_float((unsigned)scales[gi] << 23);
            Bs[SWZ(r, 2*b  )] = __float_as_uint(c_fp4[word & 15]        * f);
            Bs[SWZ(r, 2*b+1)] = __float_as_uint(c_fp4[(word >> 4) & 15] * f);
        }
        __syncthreads();
        #pragma unroll
        for (int kk = 0; kk < 32; kk += 8) {
            unsigned a[2][4], b[8][2];
            #pragma unroll
            for (int r = 0; r < 2; r++) {
                int mr = wm*32 + r*16 + (lane >> 2);
                int kc = kk + (lane & 3);
                a[r][0] = As[SWZ(mr,   kc)];
                a[r][1] = As[SWZ(mr+8, kc)];
                a[r][2] = As[SWZ(mr,   kc+4)];
                a[r][3] = As[SWZ(mr+8, kc+4)];
            }
            #pragma unroll
            for (int gg = 0; gg < 8; gg++) {
                int n = wn*64 + gg*8 + (lane >> 2);
                int kc = kk + (lane & 3);
                b[gg][0] = Bs[SWZ(n, kc)];
                b[gg][1] = Bs[SWZ(n, kc+4)];
            }
            #pragma unroll
            for (int r = 0; r < 2; r++)
                #pragma unroll
                for (int gg = 0; gg < 8; gg++)
                    mma_tf32(acc[r][gg], a[r], b[gg]);
        }
        __syncthreads();
    }

    // epilogue: bias + swiglu (c0/c1 and c2/c3 are adjacent even/odd columns)
    #pragma unroll
    for (int r = 0; r < 2; r++) {
        #pragma unroll
        for (int half = 0; half < 2; half++) {
            int m = m0 + wm*32 + r*16 + (lane >> 2) + half*8;
            if (m >= cnt) continue;
            int slot = off + m;
            #pragma unroll
            for (int gg = 0; gg < 8; gg++) {
                int gcol = nt*BN + wn*64 + gg*8 + 2*(lane & 3);
                float hg = acc[r][gg][half*2+0] + bias[(size_t)e*ROWS + gcol];
                float hl = acc[r][gg][half*2+1] + bias[(size_t)e*ROWS + gcol + 1];
                hg = fminf(hg, 7.f);
                hl = fminf(fmaxf(hl, -7.f), 7.f);
                float aa = hg * (1.f / (1.f + expf(-1.702f * hg))) * (hl + 1.f);
                g_a[(size_t)slot*IDIM + (gcol >> 1)] = aa;
            }
        }
    }
}

// ---------------- k5: tensor-core grouped GEMM mlp2 + weighted scatter ----------------
__global__ __launch_bounds__(256, 2) void k5_mlp2(
    const int* __restrict__ blocks, const int* __restrict__ scales,
    const float* __restrict__ bias, float* __restrict__ out)
{
    int e  = blockIdx.x;
    int nt = blockIdx.y;                 // H/BN = 8 tiles
    int cnt = g_counts[e];
    int m0 = blockIdx.z * BM;
    if (m0 >= cnt) return;
    int off = g_offsets[e];

    __shared__ unsigned As[BM*32];
    __shared__ unsigned Bs[BN*32];
    __shared__ int   s_tok[BM];
    __shared__ float s_w[BM];

    int tid = threadIdx.x;
    for (int i = tid; i < BM; i += 256) {
        int m = m0 + i;
        s_tok[i] = (m < cnt) ? g_slot_tok[off + m] : -1;
        s_w[i]   = (m < cnt) ? g_slot_w[off + m] : 0.f;
    }
    __syncthreads();

    int lane = tid & 31, wid = tid >> 5;
    int wm = wid >> 1, wn = wid & 1;
    float acc[2][8][4] = {};

    const int ROWS = HDIM, GRPS = IDIM/32;
    for (int k0 = 0; k0 < IDIM; k0 += BK) {
        #pragma unroll
        for (int it = 0; it < (BM*32)/256; it++) {
            int i = tid + it*256;
            int m = i >> 5, k = i & 31;
            float v = (m0 + m < cnt) ? g_a[(size_t)(off + m0 + m)*IDIM + k0 + k] : 0.f;
            As[SWZ(m, k)] = f2tf(v);
        }
        int g = k0 >> 5;
        #pragma unroll
        for (int it = 0; it < (BN*16)/256; it++) {
            int i = tid + it*256;
            int r = i >> 4, b = i & 15;
            size_t gi = ((size_t)e*ROWS + (nt*BN + r)) * GRPS + g;
            int word = blocks[gi*16 + b];
            float f = __int_as_float((unsigned)scales[gi] << 23);
            Bs[SWZ(r, 2*b  )] = __float_as_uint(c_fp4[word & 15]        * f);
            Bs[SWZ(r, 2*b+1)] = __float_as_uint(c_fp4[(word >> 4) & 15] * f);
        }
        __syncthreads();
        #pragma unroll
        for (int kk = 0; kk < 32; kk += 8) {
            unsigned a[2][4], b[8][2];
            #pragma unroll
            for (int r = 0; r < 2; r++) {
                int mr = wm*32 + r*16 + (lane >> 2);
                int kc = kk + (lane & 3);
                a[r][0] = As[SWZ(mr,   kc)];
                a[r][1] = As[SWZ(mr+8, kc)];
                a[r][2] = As[SWZ(mr,   kc+4)];
                a[r][3] = As[SWZ(mr+8, kc+4)];
            }
            #pragma unroll
            for (int gg = 0; gg < 8; gg++) {
                int n = wn*64 + gg*8 + (lane >> 2);
                int kc = kk + (lane & 3);
                b[gg][0] = Bs[SWZ(n, kc)];
                b[gg][1] = Bs[SWZ(n, kc+4)];
            }
            #pragma unroll
            for (int r = 0; r < 2; r++)
                #pragma unroll
                for (int gg = 0; gg < 8; gg++)
                    mma_tf32(acc[r][gg], a[r], b[gg]);
        }
        __syncthreads();
    }

    #pragma unroll
    for (int r = 0; r < 2; r++) {
        #pragma unroll
        for (int half = 0; half < 2; half++) {
            int mi = wm*32 + r*16 + (lane >> 2) + half*8;
            if (m0 + mi >= cnt) continue;
            int tok = s_tok[mi];
            float rw = s_w[mi];
            #pragma unroll
            for (int gg = 0; gg < 8; gg++) {
                int gcol = nt*BN + wn*64 + gg*8 + 2*(lane & 3);
                float y0 = acc[r][gg][half*2+0] + bias[(size_t)e*HDIM + gcol];
                float y1 = acc[r][gg][half*2+1] + bias[(size_t)e*HDIM + gcol + 1];
                atomicAdd(&out[(size_t)tok*HDIM + gcol],     rw * y0);
                atomicAdd(&out[(size_t)tok*HDIM + gcol + 1], rw * y1);
            }
        }
    }
}

// ---------------- launch ----------------
extern "C" void kernel_launch(void* const* d_in, const int* in_sizes, int n_in,
                              void* d_out, int out_size)
{
    const float* x          = (const float*)d_in[0];
    const float* norm_w     = (const float*)d_in[1];
    const float* gate_w     = (const float*)d_in[2];
    const float* gate_b     = (const float*)d_in[3];
    const float* mlp1_bias  = (const float*)d_in[4];
    const float* mlp2_bias  = (const float*)d_in[5];
    const int*   mlp1_blocks= (const int*)d_in[6];
    const int*   mlp1_scales= (const int*)d_in[7];
    const int*   mlp2_blocks= (const int*)d_in[8];
    const int*   mlp2_scales= (const int*)d_in[9];
    float* out = (float*)d_out;

    k0_zero<<<1, 32>>>();
    k1_norm_gate<<<N_TOK, 256>>>(x, norm_w, gate_w, gate_b, out);
    k2_scan<<<1, 1>>>();
    k3_scatter<<<NSLOT/256, 256>>>();
    dim3 g4(NEXP, (2*IDIM)/BN, N_TOK/BM);   // (32, 16, 8)
    k4_mlp1<<<g4, 256>>>(mlp1_blocks, mlp1_scales, mlp1_bias);
    dim3 g5(NEXP, HDIM/BN, N_TOK/BM);       // (32, 8, 8)
    k5_mlp2<<<g5, 256>>>(mlp2_blocks, mlp2_scales, mlp2_bias, out);
}

// round 4
// speedup vs baseline: 3.9325x; 2.5631x over previous
#include <cuda_runtime.h>
#include <math.h>
#include <stdint.h>

#define N_TOK 1024
#define HDIM  1024
#define IDIM  1024
#define NEXP  32
#define TOPK  4
#define NSLOT (N_TOK*TOPK)

#define BM 128
#define BN 128
#define BK 32
#define NK 32

// dynamic smem layout (relative to 1024-aligned base)
#define AS_OFF(s)   ((s)*16384)          // 2 x 16KB A tiles (tf32)
#define BS_OFF      32768                 // 16KB decoded B tile (tf32)
#define BRAW_OFF(s) (49152 + (s)*8192)    // 2 x 8KB raw fp4 blocks
#define SCL_OFF(s)  (65536 + (s)*512)     // 2 x 512B scales
#define DSMEM_BYTES (66560 + 1024)

// ---------------- device scratch ----------------
__device__ float g_t[N_TOK*HDIM];          // rmsnormed activations (tf32-rounded fp32)
__device__ float g_a[NSLOT*IDIM];          // swiglu outputs (tf32-rounded fp32)
__device__ int   g_counts[NEXP];
__device__ int   g_offsets[NEXP+1];
__device__ int   g_cursor[NEXP];
__device__ int   g_topidx[NSLOT];
__device__ float g_topw[NSLOT];
__device__ int   g_slot_tok[NSLOT];
__device__ float g_slot_w[NSLOT];

// ---------------- helpers ----------------
__device__ __forceinline__ uint32_t smem_u32(const void* p) {
    uint32_t a;
    asm("{ .reg .u64 t; cvta.to.shared.u64 t, %1; cvt.u32.u64 %0, t; }" : "=r"(a) : "l"(p));
    return a;
}
__device__ __forceinline__ unsigned f2tf(float f) {
    unsigned r; asm("cvt.rna.tf32.f32 %0, %1;" : "=r"(r) : "f"(f)); return r;
}
__device__ __forceinline__ void cp16(uint32_t dst, const void* src) {
    asm volatile("cp.async.cg.shared.global [%0], [%1], 16;" :: "r"(dst), "l"(src));
}
__device__ __forceinline__ void cp4(uint32_t dst, const void* src) {
    asm volatile("cp.async.ca.shared.global [%0], [%1], 4;" :: "r"(dst), "l"(src));
}
#define CP_COMMIT() asm volatile("cp.async.commit_group;" ::: "memory")
#define CP_WAIT0()  asm volatile("cp.async.wait_group 0;" ::: "memory")

__device__ __forceinline__ void ldsm4(uint32_t& r0, uint32_t& r1, uint32_t& r2, uint32_t& r3,
                                      uint32_t addr) {
    asm volatile("ldmatrix.sync.aligned.m8n8.x4.shared.b16 {%0,%1,%2,%3}, [%4];"
        : "=r"(r0), "=r"(r1), "=r"(r2), "=r"(r3) : "r"(addr));
}
__device__ __forceinline__ void mma_tf32(float c[4], const uint32_t a[4], const uint32_t b[2]) {
    asm volatile("mma.sync.aligned.m16n8k8.row.col.f32.tf32.tf32.f32 "
        "{%0,%1,%2,%3}, {%4,%5,%6,%7}, {%8,%9}, {%0,%1,%2,%3};"
        : "+f"(c[0]), "+f"(c[1]), "+f"(c[2]), "+f"(c[3])
        : "r"(a[0]), "r"(a[1]), "r"(a[2]), "r"(a[3]), "r"(b[0]), "r"(b[1]));
}

// mxfp4 nibble + E8M0 scale -> fp32 bits (exact, and exact in tf32)
__device__ __forceinline__ unsigned dec(unsigned nib, unsigned sc) {
    unsigned c = nib & 7u;
    unsigned sgn = (nib & 8u) << 28;
    unsigned mant = (c > 1u) ? ((c & 1u) << 22) : 0u;
    unsigned ex = (sc - 1u + (c >> 1)) << 23;
    return c ? (sgn | ex | mant) : sgn;
}
// SW128-style xor swizzle on byte offsets (16B granular), pitch 128B rows
__device__ __forceinline__ unsigned swz(unsigned byte) {
    return byte ^ ((byte >> 3) & 0x70u);
}

// ---------------- k0..k3 routing ----------------
__global__ void k0_zero() {
    int i = threadIdx.x;
    if (i < NEXP) { g_counts[i] = 0; g_cursor[i] = 0; }
}

__global__ __launch_bounds__(256) void k1_norm_gate(
    const float* __restrict__ x, const float* __restrict__ norm_w,
    const float* __restrict__ gate_w, const float* __restrict__ gate_b,
    float* __restrict__ out)
{
    int tok = blockIdx.x;
    int tid = threadIdx.x;
    __shared__ float s_t[HDIM];
    __shared__ float s_red[8];
    __shared__ float s_log[NEXP];

    const float* xr = x + (size_t)tok * HDIM;
    float ss = 0.f;
    for (int i = tid; i < HDIM; i += 256) { float v = xr[i]; ss += v*v; s_t[i] = v; }
    #pragma unroll
    for (int o = 16; o; o >>= 1) ss += __shfl_down_sync(0xffffffffu, ss, o);
    if ((tid & 31) == 0) s_red[tid >> 5] = ss;
    __syncthreads();
    if (tid < 8) {
        float v = s_red[tid];
        #pragma unroll
        for (int o = 4; o; o >>= 1) v += __shfl_down_sync(0xffu, v, o);
        if (tid == 0) s_red[0] = v;
    }
    __syncthreads();
    float scale = rsqrtf(s_red[0] * (1.f / HDIM) + 1e-5f);
    for (int i = tid; i < HDIM; i += 256) {
        float t = s_t[i] * scale * norm_w[i];
        s_t[i] = t;
        g_t[(size_t)tok * HDIM + i] = __uint_as_float(f2tf(t));   // pre-rounded tf32
        out[(size_t)tok * HDIM + i] = xr[i];                      // residual init
    }
    __syncthreads();

    int warp = tid >> 5, lane = tid & 31;
    for (int e = warp; e < NEXP; e += 8) {
        const float* gw = gate_w + (size_t)e * HDIM;
        float acc = 0.f;
        for (int i = lane; i < HDIM; i += 32) acc += s_t[i] * gw[i];
        #pragma unroll
        for (int o = 16; o; o >>= 1) acc += __shfl_down_sync(0xffffffffu, acc, o);
        if (lane == 0) s_log[e] = acc + gate_b[e];
    }
    __syncthreads();

    if (tid == 0) {
        int idx[TOPK]; float val[TOPK];
        unsigned mask = 0;
        #pragma unroll
        for (int k = 0; k < TOPK; k++) {
            float best = -1e30f; int bi = 0;
            for (int e = 0; e < NEXP; e++)
                if (!((mask >> e) & 1u) && s_log[e] > best) { best = s_log[e]; bi = e; }
            mask |= 1u << bi; idx[k] = bi; val[k] = best;
        }
        float mx = val[0];
        float se = 0.f;
        #pragma unroll
        for (int k = 0; k < TOPK; k++) { val[k] = expf(val[k] - mx); se += val[k]; }
        float inv = 1.f / se;
        #pragma unroll
        for (int k = 0; k < TOPK; k++) {
            g_topidx[tok*TOPK + k] = idx[k];
            g_topw[tok*TOPK + k]  = val[k] * inv;
            atomicAdd(&g_counts[idx[k]], 1);
        }
    }
}

__global__ void k2_scan() {
    if (threadIdx.x == 0) {
        int s = 0;
        for (int e = 0; e < NEXP; e++) { g_offsets[e] = s; s += g_counts[e]; }
        g_offsets[NEXP] = s;
    }
}

__global__ void k3_scatter() {
    int i = blockIdx.x * blockDim.x + threadIdx.x;
    if (i < NSLOT) {
        int e = g_topidx[i];
        int pos = g_offsets[e] + atomicAdd(&g_cursor[e], 1);
        g_slot_tok[pos] = i >> 2;
        g_slot_w[pos]   = g_topw[i];
    }
}

// ================= k4: pipelined tf32 mma grouped GEMM + swiglu =================
__global__ __launch_bounds__(256, 2) void k4_mlp1(
    const int* __restrict__ blocks, const int* __restrict__ scales,
    const float* __restrict__ bias)
{
    int e  = blockIdx.x;
    int nt = blockIdx.y;                  // 2I/BN = 16
    int cnt = g_counts[e];
    int m0 = blockIdx.z * BM;
    if (m0 >= cnt) return;
    int off = g_offsets[e];

    extern __shared__ char dsm[];
    char* sb = (char*)(((uintptr_t)dsm + 1023) & ~(uintptr_t)1023);
    uint32_t sb32 = smem_u32(sb);
    __shared__ int s_tok[BM];

    const int ROWS = 2*IDIM, GRPS = HDIM/32;
    int tid = threadIdx.x;
    int lane = tid & 31, wid = tid >> 5;
    int wm = wid >> 1, wn = wid & 1;

    for (int i = tid; i < BM; i += 256) {
        int m = m0 + i;
        s_tok[i] = (m < cnt) ? g_slot_tok[off + m] : 0;   // clamp: padded rows harmless
    }
    __syncthreads();

    // ---- load issue: stage kt&1 ----
    auto issue = [&](int kt) {
        int s = kt & 1;
        int c = tid & 7, mr = tid >> 3;
        #pragma unroll
        for (int p = 0; p < 4; p++) {
            int m = mr + p*32;
            const float* src = g_t + (size_t)s_tok[m]*HDIM + kt*BK + c*4;
            cp16(sb32 + AS_OFF(s) + swz(m*128 + c*16), src);
        }
        #pragma unroll
        for (int p = 0; p < 2; p++) {
            int ci = tid + p*256;
            int n = ci >> 2, j = ci & 3;
            const int* src = blocks + ((size_t)e*ROWS + nt*BN + n)*(size_t)GRPS*16
                                    + (size_t)kt*16 + j*4;
            cp16(sb32 + BRAW_OFF(s) + n*64 + j*16, src);
        }
        if (tid < 128) {
            const int* src = scales + ((size_t)e*ROWS + nt*BN + tid)*GRPS + kt;
            cp4(sb32 + SCL_OFF(s) + tid*4, src);
        }
        CP_COMMIT();
    };

    issue(0);
    float acc[2][8][4] = {};

    for (int kt = 0; kt < NK; kt++) {
        int s = kt & 1;
        CP_WAIT0();
        __syncthreads();
        if (kt + 1 < NK) issue(kt + 1);
        // decode raw fp4 -> tf32 Bs
        {
            int q = tid & 7;
            #pragma unroll
            for (int p = 0; p < 4; p++) {
                int n = p*32 + (tid >> 3);
                uint2 raw = *(const uint2*)(sb + BRAW_OFF(s) + n*64 + q*8);
                unsigned sc = *(const unsigned*)(sb + SCL_OFF(s) + n*4);
                uint4 u = make_uint4(dec(raw.x & 15u, sc), dec((raw.x >> 4) & 15u, sc),
                                     dec(raw.y & 15u, sc), dec((raw.y >> 4) & 15u, sc));
                *(uint4*)(sb + BS_OFF + swz(n*128 + q*16)) = u;
            }
        }
        __syncthreads();
        // mma over 4 k8 slices
        uint32_t Ab = sb32 + AS_OFF(s), Bb = sb32 + BS_OFF;
        #pragma unroll
        for (int kk = 0; kk < 4; kk++) {
            uint32_t a[2][4];
            {
                int jm = (lane >> 3) & 1, jk = lane >> 4, r = lane & 7;
                #pragma unroll
                for (int h = 0; h < 2; h++) {
                    uint32_t ad = Ab + swz((wm*32 + h*16 + jm*8 + r)*128 + kk*32 + jk*16);
                    ldsm4(a[h][0], a[h][1], a[h][2], a[h][3], ad);
                }
            }
            uint32_t b[8][2];
            {
                int jn = lane >> 4, jk2 = (lane >> 3) & 1, r = lane & 7;
                #pragma unroll
                for (int g2 = 0; g2 < 4; g2++) {
                    uint32_t ad = Bb + swz((wn*64 + g2*16 + jn*8 + r)*128 + kk*32 + jk2*16);
                    ldsm4(b[2*g2][0], b[2*g2][1], b[2*g2+1][0], b[2*g2+1][1], ad);
                }
            }
            #pragma unroll
            for (int h = 0; h < 2; h++)
                #pragma unroll
                for (int g = 0; g < 8; g++)
                    mma_tf32(acc[h][g], a[h], b[g]);
        }
    }

    // ---- epilogue: bias + swiglu, tf32-rounded store to g_a ----
    #pragma unroll
    for (int h = 0; h < 2; h++) {
        #pragma unroll
        for (int half = 0; half < 2; half++) {
            int m = m0 + wm*32 + h*16 + (lane >> 2) + half*8;
            if (m >= cnt) continue;
            int slot = off + m;
            #pragma unroll
            for (int g = 0; g < 8; g++) {
                int gcol = nt*BN + wn*64 + g*8 + 2*(lane & 3);
                float hg = acc[h][g][half*2+0] + bias[(size_t)e*ROWS + gcol];
                float hl = acc[h][g][half*2+1] + bias[(size_t)e*ROWS + gcol + 1];
                hg = fminf(hg, 7.f);
                hl = fminf(fmaxf(hl, -7.f), 7.f);
                float aa = hg * (1.f / (1.f + expf(-1.702f * hg))) * (hl + 1.f);
                g_a[(size_t)slot*IDIM + (gcol >> 1)] = __uint_as_float(f2tf(aa));
            }
        }
    }
}

// ================= k5: pipelined tf32 mma grouped GEMM + weighted scatter =================
__global__ __launch_bounds__(256, 2) void k5_mlp2(
    const int* __restrict__ blocks, const int* __restrict__ scales,
    const float* __restrict__ bias, float* __restrict__ out)
{
    int e  = blockIdx.x;
    int nt = blockIdx.y;                  // H/BN = 8
    int cnt = g_counts[e];
    int m0 = blockIdx.z * BM;
    if (m0 >= cnt) return;
    int off = g_offsets[e];

    extern __shared__ char dsm[];
    char* sb = (char*)(((uintptr_t)dsm + 1023) & ~(uintptr_t)1023);
    uint32_t sb32 = smem_u32(sb);
    __shared__ int   s_tok[BM];
    __shared__ float s_w[BM];

    const int ROWS = HDIM, GRPS = IDIM/32;
    int tid = threadIdx.x;
    int lane = tid & 31, wid = tid >> 5;
    int wm = wid >> 1, wn = wid & 1;

    for (int i = tid; i < BM; i += 256) {
        int m = m0 + i;
        s_tok[i] = (m < cnt) ? g_slot_tok[off + m] : 0;
        s_w[i]   = (m < cnt) ? g_slot_w[off + m] : 0.f;
    }
    __syncthreads();

    auto issue = [&](int kt) {
        int s = kt & 1;
        int c = tid & 7, mr = tid >> 3;
        #pragma unroll
        for (int p = 0; p < 4; p++) {
            int m = mr + p*32;
            int row = off + m0 + m;
            if (row > NSLOT-1) row = NSLOT-1;
            const float* src = g_a + (size_t)row*IDIM + kt*BK + c*4;
            cp16(sb32 + AS_OFF(s) + swz(m*128 + c*16), src);
        }
        #pragma unroll
        for (int p = 0; p < 2; p++) {
            int ci = tid + p*256;
            int n = ci >> 2, j = ci & 3;
            const int* src = blocks + ((size_t)e*ROWS + nt*BN + n)*(size_t)GRPS*16
                                    + (size_t)kt*16 + j*4;
            cp16(sb32 + BRAW_OFF(s) + n*64 + j*16, src);
        }
        if (tid < 128) {
            const int* src = scales + ((size_t)e*ROWS + nt*BN + tid)*GRPS + kt;
            cp4(sb32 + SCL_OFF(s) + tid*4, src);
        }
        CP_COMMIT();
    };

    issue(0);
    float acc[2][8][4] = {};

    for (int kt = 0; kt < NK; kt++) {
        int s = kt & 1;
        CP_WAIT0();
        __syncthreads();
        if (kt + 1 < NK) issue(kt + 1);
        {
            int q = tid & 7;
            #pragma unroll
            for (int p = 0; p < 4; p++) {
                int n = p*32 + (tid >> 3);
                uint2 raw = *(const uint2*)(sb + BRAW_OFF(s) + n*64 + q*8);
                unsigned sc = *(const unsigned*)(sb + SCL_OFF(s) + n*4);
                uint4 u = make_uint4(dec(raw.x & 15u, sc), dec((raw.x >> 4) & 15u, sc),
                                     dec(raw.y & 15u, sc), dec((raw.y >> 4) & 15u, sc));
                *(uint4*)(sb + BS_OFF + swz(n*128 + q*16)) = u;
            }
        }
        __syncthreads();
        uint32_t Ab = sb32 + AS_OFF(s), Bb = sb32 + BS_OFF;
        #pragma unroll
        for (int kk = 0; kk < 4; kk++) {
            uint32_t a[2][4];
            {
                int jm = (lane >> 3) & 1, jk = lane >> 4, r = lane & 7;
                #pragma unroll
                for (int h = 0; h < 2; h++) {
                    uint32_t ad = Ab + swz((wm*32 + h*16 + jm*8 + r)*128 + kk*32 + jk*16);
                    ldsm4(a[h][0], a[h][1], a[h][2], a[h][3], ad);
                }
            }
            uint32_t b[8][2];
            {
                int jn = lane >> 4, jk2 = (lane >> 3) & 1, r = lane & 7;
                #pragma unroll
                for (int g2 = 0; g2 < 4; g2++) {
                    uint32_t ad = Bb + swz((wn*64 + g2*16 + jn*8 + r)*128 + kk*32 + jk2*16);
                    ldsm4(b[2*g2][0], b[2*g2][1], b[2*g2+1][0], b[2*g2+1][1], ad);
                }
            }
            #pragma unroll
            for (int h = 0; h < 2; h++)
                #pragma unroll
                for (int g = 0; g < 8; g++)
                    mma_tf32(acc[h][g], a[h], b[g]);
        }
    }

    #pragma unroll
    for (int h = 0; h < 2; h++) {
        #pragma unroll
        for (int half = 0; half < 2; half++) {
            int mi = wm*32 + h*16 + (lane >> 2) + half*8;
            if (m0 + mi >= cnt) continue;
            int tok = s_tok[mi];
            float rw = s_w[mi];
            #pragma unroll
            for (int g = 0; g < 8; g++) {
                int gcol = nt*BN + wn*64 + g*8 + 2*(lane & 3);
                float y0 = acc[h][g][half*2+0] + bias[(size_t)e*HDIM + gcol];
                float y1 = acc[h][g][half*2+1] + bias[(size_t)e*HDIM + gcol + 1];
                atomicAdd(&out[(size_t)tok*HDIM + gcol],     rw * y0);
                atomicAdd(&out[(size_t)tok*HDIM + gcol + 1], rw * y1);
            }
        }
    }
}

// ---------------- launch ----------------
extern "C" void kernel_launch(void* const* d_in, const int* in_sizes, int n_in,
                              void* d_out, int out_size)
{
    const float* x          = (const float*)d_in[0];
    const float* norm_w     = (const float*)d_in[1];
    const float* gate_w     = (const float*)d_in[2];
    const float* gate_b     = (const float*)d_in[3];
    const float* mlp1_bias  = (const float*)d_in[4];
    const float* mlp2_bias  = (const float*)d_in[5];
    const int*   mlp1_blocks= (const int*)d_in[6];
    const int*   mlp1_scales= (const int*)d_in[7];
    const int*   mlp2_blocks= (const int*)d_in[8];
    const int*   mlp2_scales= (const int*)d_in[9];
    float* out = (float*)d_out;

    cudaFuncSetAttribute(k4_mlp1, cudaFuncAttributeMaxDynamicSharedMemorySize, DSMEM_BYTES);
    cudaFuncSetAttribute(k5_mlp2, cudaFuncAttributeMaxDynamicSharedMemorySize, DSMEM_BYTES);

    k0_zero<<<1, 32>>>();
    k1_norm_gate<<<N_TOK, 256>>>(x, norm_w, gate_w, gate_b, out);
    k2_scan<<<1, 1>>>();
    k3_scatter<<<NSLOT/256, 256>>>();
    dim3 g4(NEXP, (2*IDIM)/BN, N_TOK/BM);   // (32, 16, 8)
    k4_mlp1<<<g4, 256, DSMEM_BYTES>>>(mlp1_blocks, mlp1_scales, mlp1_bias);
    dim3 g5(NEXP, HDIM/BN, N_TOK/BM);       // (32, 8, 8)
    k5_mlp2<<<g5, 256, DSMEM_BYTES>>>(mlp2_blocks, mlp2_scales, mlp2_bias, out);
}

// round 5
// speedup vs baseline: 5.8845x; 1.4963x over previous
#include <cuda_runtime.h>
#include <cuda_fp16.h>
#include <math.h>
#include <stdint.h>

#define N_TOK 1024
#define HDIM  1024
#define IDIM  1024
#define NEXP  32
#define TOPK  4
#define NSLOT (N_TOK*TOPK)

#define BM 128
#define BN 128
#define BK 64
#define NK 16            // 1024 / 64

// dynamic smem layout (bytes from 1024-aligned base)
#define AS_OFF(s)   ((s)*16384)            // 2 x 16KB A tiles (fp16 128x64)
#define BS_OFF      32768                   // 16KB decoded B tile (fp16 128x64)
#define BRAW_OFF(s) (49152 + (s)*16384)     // 2 x 16KB raw blocks (int32-per-byte)
#define SCL_OFF(s)  (81920 + (s)*1024)      // 2 x 1KB scales
#define DSMEM_BYTES (84*1024 + 1024)

// ---------------- device scratch ----------------
__device__ __half g_t[N_TOK*HDIM];         // rmsnormed activations (fp16)
__device__ __half g_a[NSLOT*IDIM];         // swiglu outputs (fp16)
__device__ int    g_counts[NEXP];
__device__ int    g_offsets[NEXP+1];
__device__ int    g_cursor[NEXP];
__device__ int    g_topidx[NSLOT];
__device__ float  g_topw[NSLOT];
__device__ int    g_slot_tok[NSLOT];
__device__ float  g_slot_w[NSLOT];

// ---------------- helpers ----------------
__device__ __forceinline__ uint32_t smem_u32(const void* p) {
    uint32_t a;
    asm("{ .reg .u64 t; cvta.to.shared.u64 t, %1; cvt.u32.u64 %0, t; }" : "=r"(a) : "l"(p));
    return a;
}
__device__ __forceinline__ void cp16(uint32_t dst, const void* src) {
    asm volatile("cp.async.cg.shared.global [%0], [%1], 16;" :: "r"(dst), "l"(src));
}
__device__ __forceinline__ void cp4(uint32_t dst, const void* src) {
    asm volatile("cp.async.ca.shared.global [%0], [%1], 4;" :: "r"(dst), "l"(src));
}
#define CP_COMMIT() asm volatile("cp.async.commit_group;" ::: "memory")
#define CP_WAIT0()  asm volatile("cp.async.wait_group 0;" ::: "memory")

__device__ __forceinline__ void ldsm4(uint32_t& r0, uint32_t& r1, uint32_t& r2, uint32_t& r3,
                                      uint32_t addr) {
    asm volatile("ldmatrix.sync.aligned.m8n8.x4.shared.b16 {%0,%1,%2,%3}, [%4];"
        : "=r"(r0), "=r"(r1), "=r"(r2), "=r"(r3) : "r"(addr));
}
__device__ __forceinline__ void mma_fp16(float c[4], const uint32_t a[4], const uint32_t b[2]) {
    asm volatile("mma.sync.aligned.m16n8k16.row.col.f32.f16.f16.f32 "
        "{%0,%1,%2,%3}, {%4,%5,%6,%7}, {%8,%9}, {%0,%1,%2,%3};"
        : "+f"(c[0]), "+f"(c[1]), "+f"(c[2]), "+f"(c[3])
        : "r"(a[0]), "r"(a[1]), "r"(a[2]), "r"(a[3]), "r"(b[0]), "r"(b[1]));
}

// mxfp4 nibble + E8M0 scale -> fp16 bits (exact)
__device__ __forceinline__ unsigned dec16(unsigned nib, unsigned sc) {
    unsigned c = nib & 7u;
    unsigned sgn = (nib & 8u) << 12;
    unsigned mant = (c > 1u) ? ((c & 1u) << 9) : 0u;
    unsigned ex = (sc - 113u + (c >> 1)) << 10;
    return c ? (sgn | ex | mant) : sgn;
}
// SW128 xor swizzle (128B rows, 16B chunks)
__device__ __forceinline__ unsigned swz(unsigned byte) {
    return byte ^ ((byte >> 3) & 0x70u);
}

// ---------------- k0..k3 routing ----------------
__global__ void k0_zero() {
    int i = threadIdx.x;
    if (i < NEXP) { g_counts[i] = 0; g_cursor[i] = 0; }
}

__global__ __launch_bounds__(256) void k1_norm_gate(
    const float* __restrict__ x, const float* __restrict__ norm_w,
    const float* __restrict__ gate_w, const float* __restrict__ gate_b,
    float* __restrict__ out)
{
    int tok = blockIdx.x;
    int tid = threadIdx.x;
    __shared__ float s_t[HDIM];
    __shared__ float s_red[8];
    __shared__ float s_log[NEXP];

    const float* xr = x + (size_t)tok * HDIM;
    float ss = 0.f;
    for (int i = tid; i < HDIM; i += 256) { float v = xr[i]; ss += v*v; s_t[i] = v; }
    #pragma unroll
    for (int o = 16; o; o >>= 1) ss += __shfl_down_sync(0xffffffffu, ss, o);
    if ((tid & 31) == 0) s_red[tid >> 5] = ss;
    __syncthreads();
    if (tid < 8) {
        float v = s_red[tid];
        #pragma unroll
        for (int o = 4; o; o >>= 1) v += __shfl_down_sync(0xffu, v, o);
        if (tid == 0) s_red[0] = v;
    }
    __syncthreads();
    float scale = rsqrtf(s_red[0] * (1.f / HDIM) + 1e-5f);
    for (int i = tid; i < HDIM; i += 256) {
        float t = s_t[i] * scale * norm_w[i];
        s_t[i] = t;
        g_t[(size_t)tok * HDIM + i] = __float2half_rn(t);
        out[(size_t)tok * HDIM + i] = xr[i];   // residual init
    }
    __syncthreads();

    int warp = tid >> 5, lane = tid & 31;
    for (int e = warp; e < NEXP; e += 8) {
        const float* gw = gate_w + (size_t)e * HDIM;
        float acc = 0.f;
        for (int i = lane; i < HDIM; i += 32) acc += s_t[i] * gw[i];
        #pragma unroll
        for (int o = 16; o; o >>= 1) acc += __shfl_down_sync(0xffffffffu, acc, o);
        if (lane == 0) s_log[e] = acc + gate_b[e];
    }
    __syncthreads();

    if (tid == 0) {
        int idx[TOPK]; float val[TOPK];
        unsigned mask = 0;
        #pragma unroll
        for (int k = 0; k < TOPK; k++) {
            float best = -1e30f; int bi = 0;
            for (int e = 0; e < NEXP; e++)
                if (!((mask >> e) & 1u) && s_log[e] > best) { best = s_log[e]; bi = e; }
            mask |= 1u << bi; idx[k] = bi; val[k] = best;
        }
        float mx = val[0];
        float se = 0.f;
        #pragma unroll
        for (int k = 0; k < TOPK; k++) { val[k] = expf(val[k] - mx); se += val[k]; }
        float inv = 1.f / se;
        #pragma unroll
        for (int k = 0; k < TOPK; k++) {
            g_topidx[tok*TOPK + k] = idx[k];
            g_topw[tok*TOPK + k]  = val[k] * inv;
            atomicAdd(&g_counts[idx[k]], 1);
        }
    }
}

__global__ void k2_scan() {
    if (threadIdx.x == 0) {
        int s = 0;
        for (int e = 0; e < NEXP; e++) { g_offsets[e] = s; s += g_counts[e]; }
        g_offsets[NEXP] = s;
    }
}

__global__ void k3_scatter() {
    int i = blockIdx.x * blockDim.x + threadIdx.x;
    if (i < NSLOT) {
        int e = g_topidx[i];
        int pos = g_offsets[e] + atomicAdd(&g_cursor[e], 1);
        g_slot_tok[pos] = i >> 2;
        g_slot_w[pos]   = g_topw[i];
    }
}

// ================= k4: fp16 mma grouped GEMM + swiglu =================
__global__ __launch_bounds__(256, 2) void k4_mlp1(
    const int* __restrict__ blocks, const int* __restrict__ scales,
    const float* __restrict__ bias)
{
    int e  = blockIdx.x;
    int nt = blockIdx.y;                  // 2I/BN = 16
    int cnt = g_counts[e];
    int m0 = blockIdx.z * BM;
    if (m0 >= cnt) return;
    int off = g_offsets[e];

    extern __shared__ char dsm[];
    char* sb = (char*)(((uintptr_t)dsm + 1023) & ~(uintptr_t)1023);
    uint32_t sb32 = smem_u32(sb);
    __shared__ int s_tok[BM];

    const int ROWS = 2*IDIM, GRPS = HDIM/32;
    int tid = threadIdx.x;
    int lane = tid & 31, wid = tid >> 5;
    int wm = wid >> 1, wn = wid & 1;

    for (int i = tid; i < BM; i += 256) {
        int m = m0 + i;
        s_tok[i] = (m < cnt) ? g_slot_tok[off + m] : 0;
    }
    __syncthreads();

    auto issue = [&](int kt) {
        int s = kt & 1;
        int c = tid & 7, mr = tid >> 3;
        #pragma unroll
        for (int p = 0; p < 4; p++) {
            int m = mr + p*32;
            const __half* src = g_t + (size_t)s_tok[m]*HDIM + kt*BK + c*8;
            cp16(sb32 + AS_OFF(s) + swz(m*128 + c*16), src);
        }
        #pragma unroll
        for (int p = 0; p < 4; p++) {
            int ci = tid + p*256;
            int n = ci >> 3, j = ci & 7;
            const int* src = blocks + ((size_t)e*ROWS + nt*BN + n)*(size_t)GRPS*16
                                    + (size_t)(kt*2)*16 + j*4;
            cp16(sb32 + BRAW_OFF(s) + swz(n*128 + j*16), src);
        }
        {
            int row = tid >> 1, g = tid & 1;
            const int* src = scales + ((size_t)e*ROWS + nt*BN + row)*GRPS + kt*2 + g;
            cp4(sb32 + SCL_OFF(s) + tid*4, src);
        }
        CP_COMMIT();
    };

    issue(0);
    float acc[2][8][4] = {};

    for (int kt = 0; kt < NK; kt++) {
        int s = kt & 1;
        CP_WAIT0();
        __syncthreads();
        if (kt + 1 < NK) issue(kt + 1);
        // decode raw fp4 -> fp16 Bs (each thread: half a row = 32 values)
        {
            int n = tid >> 1, hh = tid & 1;
            unsigned sc = *(const unsigned*)(sb + SCL_OFF(s) + (n*2 + hh)*4);
            #pragma unroll
            for (int q = 0; q < 4; q++) {
                uint4 raw = *(const uint4*)(sb + BRAW_OFF(s) + swz(n*128 + hh*64 + q*16));
                uint4 o;
                o.x = dec16(raw.x & 15u, sc) | (dec16((raw.x >> 4) & 15u, sc) << 16);
                o.y = dec16(raw.y & 15u, sc) | (dec16((raw.y >> 4) & 15u, sc) << 16);
                o.z = dec16(raw.z & 15u, sc) | (dec16((raw.z >> 4) & 15u, sc) << 16);
                o.w = dec16(raw.w & 15u, sc) | (dec16((raw.w >> 4) & 15u, sc) << 16);
                *(uint4*)(sb + BS_OFF + swz(n*128 + hh*64 + q*16)) = o;
            }
        }
        __syncthreads();
        uint32_t Ab = sb32 + AS_OFF(s), Bb = sb32 + BS_OFF;
        #pragma unroll
        for (int kk = 0; kk < 4; kk++) {          // 4 x k16
            uint32_t a[2][4];
            {
                int r = lane & 7, sel = (lane >> 3) & 1, ks = lane >> 4;
                #pragma unroll
                for (int h = 0; h < 2; h++) {
                    uint32_t ad = Ab + swz((wm*32 + h*16 + sel*8 + r)*128 + kk*32 + ks*16);
                    ldsm4(a[h][0], a[h][1], a[h][2], a[h][3], ad);
                }
            }
            uint32_t b[8][2];
            {
                int r = lane & 7, kb = (lane >> 3) & 1, nb = lane >> 4;
                #pragma unroll
                for (int g2 = 0; g2 < 4; g2++) {
                    uint32_t ad = Bb + swz((wn*64 + g2*16 + nb*8 + r)*128 + kk*32 + kb*16);
                    ldsm4(b[2*g2][0], b[2*g2][1], b[2*g2+1][0], b[2*g2+1][1], ad);
                }
            }
            #pragma unroll
            for (int h = 0; h < 2; h++)
                #pragma unroll
                for (int g = 0; g < 8; g++)
                    mma_fp16(acc[h][g], a[h], b[g]);
        }
    }

    // ---- epilogue: bias + swiglu -> g_a (fp16) ----
    #pragma unroll
    for (int h = 0; h < 2; h++) {
        #pragma unroll
        for (int half = 0; half < 2; half++) {
            int m = m0 + wm*32 + h*16 + (lane >> 2) + half*8;
            if (m >= cnt) continue;
            int slot = off + m;
            #pragma unroll
            for (int g = 0; g < 8; g++) {
                int gcol = nt*BN + wn*64 + g*8 + 2*(lane & 3);
                float hg = acc[h][g][half*2+0] + bias[(size_t)e*ROWS + gcol];
                float hl = acc[h][g][half*2+1] + bias[(size_t)e*ROWS + gcol + 1];
                hg = fminf(hg, 7.f);
                hl = fminf(fmaxf(hl, -7.f), 7.f);
                float aa = hg * (1.f / (1.f + expf(-1.702f * hg))) * (hl + 1.f);
                g_a[(size_t)slot*IDIM + (gcol >> 1)] = __float2half_rn(aa);
            }
        }
    }
}

// ================= k5: fp16 mma grouped GEMM + weighted scatter =================
__global__ __launch_bounds__(256, 2) void k5_mlp2(
    const int* __restrict__ blocks, const int* __restrict__ scales,
    const float* __restrict__ bias, float* __restrict__ out)
{
    int e  = blockIdx.x;
    int nt = blockIdx.y;                  // H/BN = 8
    int cnt = g_counts[e];
    int m0 = blockIdx.z * BM;
    if (m0 >= cnt) return;
    int off = g_offsets[e];

    extern __shared__ char dsm[];
    char* sb = (char*)(((uintptr_t)dsm + 1023) & ~(uintptr_t)1023);
    uint32_t sb32 = smem_u32(sb);
    __shared__ int   s_tok[BM];
    __shared__ float s_w[BM];

    const int ROWS = HDIM, GRPS = IDIM/32;
    int tid = threadIdx.x;
    int lane = tid & 31, wid = tid >> 5;
    int wm = wid >> 1, wn = wid & 1;

    for (int i = tid; i < BM; i += 256) {
        int m = m0 + i;
        s_tok[i] = (m < cnt) ? g_slot_tok[off + m] : 0;
        s_w[i]   = (m < cnt) ? g_slot_w[off + m] : 0.f;
    }
    __syncthreads();

    auto issue = [&](int kt) {
        int s = kt & 1;
        int c = tid & 7, mr = tid >> 3;
        #pragma unroll
        for (int p = 0; p < 4; p++) {
            int m = mr + p*32;
            int row = off + m0 + m;
            if (row > NSLOT-1) row = NSLOT-1;
            const __half* src = g_a + (size_t)row*IDIM + kt*BK + c*8;
            cp16(sb32 + AS_OFF(s) + swz(m*128 + c*16), src);
        }
        #pragma unroll
        for (int p = 0; p < 4; p++) {
            int ci = tid + p*256;
            int n = ci >> 3, j = ci & 7;
            const int* src = blocks + ((size_t)e*ROWS + nt*BN + n)*(size_t)GRPS*16
                                    + (size_t)(kt*2)*16 + j*4;
            cp16(sb32 + BRAW_OFF(s) + swz(n*128 + j*16), src);
        }
        {
            int row = tid >> 1, g = tid & 1;
            const int* src = scales + ((size_t)e*ROWS + nt*BN + row)*GRPS + kt*2 + g;
            cp4(sb32 + SCL_OFF(s) + tid*4, src);
        }
        CP_COMMIT();
    };

    issue(0);
    float acc[2][8][4] = {};

    for (int kt = 0; kt < NK; kt++) {
        int s = kt & 1;
        CP_WAIT0();
        __syncthreads();
        if (kt + 1 < NK) issue(kt + 1);
        {
            int n = tid >> 1, hh = tid & 1;
            unsigned sc = *(const unsigned*)(sb + SCL_OFF(s) + (n*2 + hh)*4);
            #pragma unroll
            for (int q = 0; q < 4; q++) {
                uint4 raw = *(const uint4*)(sb + BRAW_OFF(s) + swz(n*128 + hh*64 + q*16));
                uint4 o;
                o.x = dec16(raw.x & 15u, sc) | (dec16((raw.x >> 4) & 15u, sc) << 16);
                o.y = dec16(raw.y & 15u, sc) | (dec16((raw.y >> 4) & 15u, sc) << 16);
                o.z = dec16(raw.z & 15u, sc) | (dec16((raw.z >> 4) & 15u, sc) << 16);
                o.w = dec16(raw.w & 15u, sc) | (dec16((raw.w >> 4) & 15u, sc) << 16);
                *(uint4*)(sb + BS_OFF + swz(n*128 + hh*64 + q*16)) = o;
            }
        }
        __syncthreads();
        uint32_t Ab = sb32 + AS_OFF(s), Bb = sb32 + BS_OFF;
        #pragma unroll
        for (int kk = 0; kk < 4; kk++) {
            uint32_t a[2][4];
            {
                int r = lane & 7, sel = (lane >> 3) & 1, ks = lane >> 4;
                #pragma unroll
                for (int h = 0; h < 2; h++) {
                    uint32_t ad = Ab + swz((wm*32 + h*16 + sel*8 + r)*128 + kk*32 + ks*16);
                    ldsm4(a[h][0], a[h][1], a[h][2], a[h][3], ad);
                }
            }
            uint32_t b[8][2];
            {
                int r = lane & 7, kb = (lane >> 3) & 1, nb = lane >> 4;
                #pragma unroll
                for (int g2 = 0; g2 < 4; g2++) {
                    uint32_t ad = Bb + swz((wn*64 + g2*16 + nb*8 + r)*128 + kk*32 + kb*16);
                    ldsm4(b[2*g2][0], b[2*g2][1], b[2*g2+1][0], b[2*g2+1][1], ad);
                }
            }
            #pragma unroll
            for (int h = 0; h < 2; h++)
                #pragma unroll
                for (int g = 0; g < 8; g++)
                    mma_fp16(acc[h][g], a[h], b[g]);
        }
    }

    #pragma unroll
    for (int h = 0; h < 2; h++) {
        #pragma unroll
        for (int half = 0; half < 2; half++) {
            int mi = wm*32 + h*16 + (lane >> 2) + half*8;
            if (m0 + mi >= cnt) continue;
            int tok = s_tok[mi];
            float rw = s_w[mi];
            #pragma unroll
            for (int g = 0; g < 8; g++) {
                int gcol = nt*BN + wn*64 + g*8 + 2*(lane & 3);
                float y0 = acc[h][g][half*2+0] + bias[(size_t)e*HDIM + gcol];
                float y1 = acc[h][g][half*2+1] + bias[(size_t)e*HDIM + gcol + 1];
                atomicAdd(&out[(size_t)tok*HDIM + gcol],     rw * y0);
                atomicAdd(&out[(size_t)tok*HDIM + gcol + 1], rw * y1);
            }
        }
    }
}

// ---------------- launch ----------------
extern "C" void kernel_launch(void* const* d_in, const int* in_sizes, int n_in,
                              void* d_out, int out_size)
{
    const float* x          = (const float*)d_in[0];
    const float* norm_w     = (const float*)d_in[1];
    const float* gate_w     = (const float*)d_in[2];
    const float* gate_b     = (const float*)d_in[3];
    const float* mlp1_bias  = (const float*)d_in[4];
    const float* mlp2_bias  = (const float*)d_in[5];
    const int*   mlp1_blocks= (const int*)d_in[6];
    const int*   mlp1_scales= (const int*)d_in[7];
    const int*   mlp2_blocks= (const int*)d_in[8];
    const int*   mlp2_scales= (const int*)d_in[9];
    float* out = (float*)d_out;

    cudaFuncSetAttribute(k4_mlp1, cudaFuncAttributeMaxDynamicSharedMemorySize, DSMEM_BYTES);
    cudaFuncSetAttribute(k5_mlp2, cudaFuncAttributeMaxDynamicSharedMemorySize, DSMEM_BYTES);

    k0_zero<<<1, 32>>>();
    k1_norm_gate<<<N_TOK, 256>>>(x, norm_w, gate_w, gate_b, out);
    k2_scan<<<1, 1>>>();
    k3_scatter<<<NSLOT/256, 256>>>();
    dim3 g4(NEXP, (2*IDIM)/BN, N_TOK/BM);   // (32, 16, 8)
    k4_mlp1<<<g4, 256, DSMEM_BYTES>>>(mlp1_blocks, mlp1_scales, mlp1_bias);
    dim3 g5(NEXP, HDIM/BN, N_TOK/BM);       // (32, 8, 8)
    k5_mlp2<<<g5, 256, DSMEM_BYTES>>>(mlp2_blocks, mlp2_scales, mlp2_bias, out);
}